// round 11
// baseline (speedup 1.0000x reference)
#include <cuda_runtime.h>
#include <cuda_fp16.h>
#include <cstdint>

// Problem dims (fixed by the reference)
#define BB   16
#define TT   512
#define HH   512
#define BT   (BB*TT)        // 8192
#define NH   8
#define DH   64
#define NBH  (BB*NH)        // 128

typedef __half fp16;

#define PLANE_ACT ((size_t)BT*HH)          // 4,194,304
#define PLANE_P   ((size_t)NBH*TT*TT)      // 33,554,432
#define PLANE_VT  ((size_t)BB*HH*TT)       // 4,194,304
#define PLANE_W   ((size_t)HH*HH)          // 262,144

// ---------------------------------------------------------------------------
// Scratch (static device globals — no allocation)
// ---------------------------------------------------------------------------
__device__ float g_S  [(size_t)NBH*TT*TT];   // fp32 scores
__device__ float g_Vf [PLANE_ACT];           // fp32 V (pre-transpose)
__device__ float g_WX [PLANE_ACT];           // fp32 LIF drive
__device__ float g_psum[256*HH];
__device__ float g_psq [256*HH];
__device__ float g_sum[HH];
__device__ float g_sq [HH];

__device__ fp16 g_vS [3*PLANE_ACT];
__device__ fp16 g_aS [3*PLANE_ACT];
__device__ fp16 g_QS [3*PLANE_ACT];
__device__ fp16 g_KS [3*PLANE_ACT];
__device__ fp16 g_OS [3*PLANE_ACT];
__device__ fp16 g_XS [3*PLANE_ACT];
__device__ fp16 g_PS [3*PLANE_P];
__device__ fp16 g_VtS[3*PLANE_VT];
__device__ fp16 g_WqT[3*PLANE_W];
__device__ fp16 g_WkT[3*PLANE_W];
__device__ fp16 g_WvT[3*PLANE_W];
__device__ fp16 g_WoT[3*PLANE_W];
__device__ fp16 g_WT [3*PLANE_W];

// ---------------------------------------------------------------------------
// Helpers
// ---------------------------------------------------------------------------
__device__ __forceinline__ uint32_t smem_u32(const void* p) {
    uint32_t a;
    asm("{ .reg .u64 t; cvta.to.shared.u64 t, %1; cvt.u32.u64 %0, t; }"
        : "=r"(a) : "l"(p));
    return a;
}
__device__ __forceinline__ void cpa16(uint32_t d, const void* s) {
    asm volatile("cp.async.ca.shared.global [%0], [%1], 16;" :: "r"(d), "l"(s));
}
#define CP_COMMIT() asm volatile("cp.async.commit_group;" ::: "memory")
#define CP_WAIT1()  asm volatile("cp.async.wait_group 1;" ::: "memory")

__device__ __forceinline__ void ldsm4(uint32_t& r0, uint32_t& r1,
                                      uint32_t& r2, uint32_t& r3, uint32_t a) {
    asm volatile("ldmatrix.sync.aligned.m8n8.x4.shared.b16 {%0,%1,%2,%3}, [%4];"
                 : "=r"(r0), "=r"(r1), "=r"(r2), "=r"(r3) : "r"(a));
}
__device__ __forceinline__ void mma16816(float* c, const uint32_t* a,
                                         uint32_t b0, uint32_t b1) {
    asm volatile(
        "mma.sync.aligned.m16n8k16.row.col.f32.f16.f16.f32 "
        "{%0,%1,%2,%3}, {%4,%5,%6,%7}, {%8,%9}, {%0,%1,%2,%3};"
        : "+f"(c[0]), "+f"(c[1]), "+f"(c[2]), "+f"(c[3])
        : "r"(a[0]), "r"(a[1]), "r"(a[2]), "r"(a[3]), "r"(b0), "r"(b1));
}

// 3-way fp16 split (33 mantissa bits; residual ~2^-33 relative)
__device__ __forceinline__ void split3h(float x, fp16& h0, fp16& h1, fp16& h2) {
    h0 = __float2half_rn(x);
    float r = x - __half2float(h0);
    h1 = __float2half_rn(r);
    r -= __half2float(h1);
    h2 = __float2half_rn(r);
}

// ---------------------------------------------------------------------------
// Accurate expf, immune to --use_fast_math.
// ---------------------------------------------------------------------------
__device__ __forceinline__ float exp_acc(float x) {
    x = fmaxf(x, -87.0f);
    float z = x * 1.44269504088896341f;
    float n = rintf(z);
    float f = fmaf(n, -0.693145751953125f, x);
    f = fmaf(n, -1.428606765330187e-06f, f);
    float p = 1.9841269841e-4f;
    p = fmaf(p, f, 1.3888888889e-3f);
    p = fmaf(p, f, 8.3333333333e-3f);
    p = fmaf(p, f, 4.1666666667e-2f);
    p = fmaf(p, f, 1.6666666667e-1f);
    p = fmaf(p, f, 0.5f);
    p = fmaf(p, f, 1.0f);
    p = fmaf(p, f, 1.0f);
    int ni = (int)n;
    float sc = __int_as_float((ni + 127) << 23);
    return p * sc;
}

// ---------------------------------------------------------------------------
// HMMA split-fp16 GEMM (mma.sync m16n8k16 f16).
//   6 products {00,01,10,11,02,20}; two accumulator banks (main (0,0) bank
//   plain fp32 accumulation — proven flip-free; small-products bank separate).
//   BM=128, BN=64, BK=32 chunks, 256 thr (8 warps: 4M x 2N), 2-stage cp.async.
//   2 CTAs/SM (46KB/stage) so one CTA computes while the other barriers.
//   EPI: 0 = fp32 C;  1 = 3 fp16 split planes (+ optional fp32 residual).
// ---------------------------------------------------------------------------
template<int EPI, bool RESID>
__global__ __launch_bounds__(256, 2)
void tgemm(const fp16* __restrict__ A, long planeA,
           const fp16* __restrict__ B, long planeB,
           float* __restrict__ Cf, fp16* __restrict__ Cs, long planeC,
           const float* __restrict__ R,
           int K, int lda, int ldb, int ldc, float alpha,
           int heads, long sAb, long sAh, long sBb, long sBh,
           long sCb, long sCh)
{
    constexpr int BN   = 64;
    constexpr int APL  = 128 * 80;         // bytes per A plane (80B pitch rows)
    constexpr int BPL  = BN * 80;
    constexpr int ASET = 3 * APL;
    constexpr int STAGE = ASET + 3 * BPL;  // 46,080 B

    extern __shared__ __align__(16) char smem[];
    const uint32_t sb = smem_u32(smem);

    const int tid = threadIdx.x, wid = tid >> 5, lane = tid & 31;
    const int wm = wid & 3, wn = wid >> 2;           // 4 x 2 warp grid
    const int z = blockIdx.z, zb = z / heads, zh = z - zb * heads;
    A += (size_t)zb * sAb + (size_t)zh * sAh;
    B += (size_t)zb * sBb + (size_t)zh * sBh;
    const size_t coff = (size_t)zb * sCb + (size_t)zh * sCh;
    const int m0 = blockIdx.y * 128, n0 = blockIdx.x * BN;
    const int nch = K >> 5;

    auto loadStageG = [&](int ch) {
        if (ch < nch) {
            const int k0 = ch * 32;
            const uint32_t ab = sb + (ch & 1) * STAGE;
            #pragma unroll
            for (int it = 0; it < 6; it++) {
                int idx = tid + it * 256;              // 0..1535 (A chunks)
                int p = idx >> 9, rem = idx & 511, r = rem >> 2, c = rem & 3;
                cpa16(ab + p * APL + r * 80 + c * 16,
                      A + (size_t)p * planeA + (size_t)(m0 + r) * lda + k0 + c * 8);
            }
            const uint32_t bb = ab + ASET;
            #pragma unroll
            for (int it = 0; it < 3; it++) {
                int idx = tid + it * 256;              // 0..767 (B chunks)
                int p = idx >> 8, rem = idx & 255, r = rem >> 2, c = rem & 3;
                cpa16(bb + p * BPL + r * 80 + c * 16,
                      B + (size_t)p * planeB + (size_t)(n0 + r) * ldb + k0 + c * 8);
            }
        }
        CP_COMMIT();
    };

    float accA[2][4][4], accB[2][4][4];
    #pragma unroll
    for (int i = 0; i < 2; i++)
        #pragma unroll
        for (int j = 0; j < 4; j++)
            #pragma unroll
            for (int q = 0; q < 4; q++) { accA[i][j][q] = 0.f; accB[i][j][q] = 0.f; }

    loadStageG(0);

    const int lrow = lane & 15;
    const int lcol = (lane >> 4) << 4;

    for (int ch = 0; ch < nch; ch++) {
        loadStageG(ch + 1);
        CP_WAIT1();
        __syncthreads();

        const uint32_t ab = sb + (ch & 1) * STAGE;
        const uint32_t bb = ab + ASET;
        const uint32_t arow = (wm * 32 + lrow) * 80 + lcol;
        const uint32_t brow = (wn * 32 + lrow) * 80 + lcol;

        #pragma unroll
        for (int ks = 0; ks < 2; ks++) {
            uint32_t af[3][2][4];
            #pragma unroll
            for (int pa = 0; pa < 3; pa++)
                #pragma unroll
                for (int mt = 0; mt < 2; mt++)
                    ldsm4(af[pa][mt][0], af[pa][mt][1], af[pa][mt][2], af[pa][mt][3],
                          ab + pa * APL + arow + mt * (16 * 80) + ks * 32);
            #pragma unroll
            for (int pb = 0; pb < 3; pb++) {
                uint32_t bf[2][4];
                #pragma unroll
                for (int tp = 0; tp < 2; tp++)
                    ldsm4(bf[tp][0], bf[tp][1], bf[tp][2], bf[tp][3],
                          bb + pb * BPL + brow + tp * (16 * 80) + ks * 32);
                #pragma unroll
                for (int pa = 0; pa < 3 - pb; pa++) {
                    #pragma unroll
                    for (int mt = 0; mt < 2; mt++)
                        #pragma unroll
                        for (int tp = 0; tp < 2; tp++) {
                            float* c0 = (pa == 0 && pb == 0)
                                      ? accA[mt][2*tp]   : accB[mt][2*tp];
                            float* c1 = (pa == 0 && pb == 0)
                                      ? accA[mt][2*tp+1] : accB[mt][2*tp+1];
                            mma16816(c0, af[pa][mt], bf[tp][0], bf[tp][2]);
                            mma16816(c1, af[pa][mt], bf[tp][1], bf[tp][3]);
                        }
                }
            }
        }
        __syncthreads();
    }

    // ---- epilogue: res = accA + accB
    Cf += coff; Cs += coff;
    if (RESID) R += coff;
    const int quad = lane >> 2, tq = lane & 3;
    #pragma unroll
    for (int mt = 0; mt < 2; mt++) {
        #pragma unroll
        for (int nt = 0; nt < 4; nt++) {
            const int col = n0 + wn * 32 + nt * 8 + tq * 2;
            #pragma unroll
            for (int h = 0; h < 2; h++) {
                const int row = m0 + wm * 32 + mt * 16 + quad + h * 8;
                float x0 = (accA[mt][nt][2*h]   + accB[mt][nt][2*h])   * alpha;
                float x1 = (accA[mt][nt][2*h+1] + accB[mt][nt][2*h+1]) * alpha;
                const size_t off = (size_t)row * ldc + col;
                if (RESID) {
                    float2 rv = *reinterpret_cast<const float2*>(R + off);
                    x0 += rv.x; x1 += rv.y;
                }
                if (EPI == 0) {
                    *reinterpret_cast<float2*>(Cf + off) = make_float2(x0, x1);
                } else {
                    fp16 a0, a1, a2, b0, b1, b2;
                    split3h(x0, a0, a1, a2);
                    split3h(x1, b0, b1, b2);
                    *reinterpret_cast<__half2*>(Cs + off)
                        = __halves2half2(a0, b0);
                    *reinterpret_cast<__half2*>(Cs + planeC + off)
                        = __halves2half2(a1, b1);
                    *reinterpret_cast<__half2*>(Cs + 2 * planeC + off)
                        = __halves2half2(a2, b2);
                }
            }
        }
    }
}

// ---------------------------------------------------------------------------
// fp32 -> 3 fp16 planes (elementwise, for inputs v and a)
// ---------------------------------------------------------------------------
__global__ __launch_bounds__(256)
void split_act(const float* __restrict__ src, fp16* __restrict__ dst, long plane)
{
    size_t i = (size_t)blockIdx.x * 256 + threadIdx.x;     // float4 index
    float4 x = reinterpret_cast<const float4*>(src)[i];
    fp16 p[3][4];
    split3h(x.x, p[0][0], p[1][0], p[2][0]);
    split3h(x.y, p[0][1], p[1][1], p[2][1]);
    split3h(x.z, p[0][2], p[1][2], p[2][2]);
    split3h(x.w, p[0][3], p[1][3], p[2][3]);
    #pragma unroll
    for (int q = 0; q < 3; q++) {
        __half2* d = reinterpret_cast<__half2*>(dst + q * plane) + i * 2;
        d[0] = __halves2half2(p[q][0], p[q][1]);
        d[1] = __halves2half2(p[q][2], p[q][3]);
    }
}

// ---------------------------------------------------------------------------
// transpose + split of the five 512x512 weights (B operands want [N,K])
// ---------------------------------------------------------------------------
struct W5 { const float* s[5]; fp16* d[5]; };

__global__ __launch_bounds__(256)
void wsplit(W5 args)
{
    __shared__ float t[32][33];
    const float* S = args.s[blockIdx.z];
    fp16* D = args.d[blockIdx.z];
    int tx = threadIdx.x & 31, ty = threadIdx.x >> 5;
    int c0 = blockIdx.x * 32, r0 = blockIdx.y * 32;
    #pragma unroll
    for (int i = 0; i < 4; i++)
        t[ty + i * 8][tx] = S[(size_t)(r0 + ty + i * 8) * 512 + c0 + tx];
    __syncthreads();
    #pragma unroll
    for (int i = 0; i < 4; i++) {
        int no = c0 + ty + i * 8;
        int ko = r0 + tx;
        fp16 b0, b1, b2;
        split3h(t[tx][ty + i * 8], b0, b1, b2);
        D[(size_t)no * 512 + ko]                 = b0;
        D[PLANE_W + (size_t)no * 512 + ko]       = b1;
        D[2 * PLANE_W + (size_t)no * 512 + ko]   = b2;
    }
}

// ---------------------------------------------------------------------------
// V[b,t,d] -> Vt planes [b,d,t] (transpose per batch + split)
// ---------------------------------------------------------------------------
__global__ __launch_bounds__(256)
void vtrans_split(const float* __restrict__ V, fp16* __restrict__ D)
{
    __shared__ float t[32][33];
    int b = blockIdx.z;
    const float* S = V + (size_t)b * TT * HH;
    fp16* Db = D + (size_t)b * HH * TT;
    int tx = threadIdx.x & 31, ty = threadIdx.x >> 5;
    int c0 = blockIdx.x * 32, r0 = blockIdx.y * 32;    // c = d, r = t
    #pragma unroll
    for (int i = 0; i < 4; i++)
        t[ty + i * 8][tx] = S[(size_t)(r0 + ty + i * 8) * 512 + c0 + tx];
    __syncthreads();
    #pragma unroll
    for (int i = 0; i < 4; i++) {
        int dd = c0 + ty + i * 8;
        int tt = r0 + tx;
        fp16 b0, b1, b2;
        split3h(t[tx][ty + i * 8], b0, b1, b2);
        Db[(size_t)dd * 512 + tt]                  = b0;
        Db[PLANE_VT + (size_t)dd * 512 + tt]       = b1;
        Db[2 * PLANE_VT + (size_t)dd * 512 + tt]   = b2;
    }
}

// ---------------------------------------------------------------------------
// Row softmax (512) fused with 3-way split output.
// ---------------------------------------------------------------------------
__global__ __launch_bounds__(128)
void softmax_split(const float* __restrict__ S, fp16* __restrict__ P)
{
    __shared__ float red[8];
    const int t = threadIdx.x;
    const float* p = S + (size_t)blockIdx.x * 512;

    float x0 = p[t], x1 = p[t + 128], x2 = p[t + 256], x3 = p[t + 384];
    float m = fmaxf(fmaxf(x0, x1), fmaxf(x2, x3));
    #pragma unroll
    for (int o = 16; o; o >>= 1)
        m = fmaxf(m, __shfl_xor_sync(0xffffffffu, m, o));
    if ((t & 31) == 0) red[t >> 5] = m;
    __syncthreads();
    m = fmaxf(fmaxf(red[0], red[1]), fmaxf(red[2], red[3]));

    float e0 = exp_acc(x0 - m), e1 = exp_acc(x1 - m);
    float e2 = exp_acc(x2 - m), e3 = exp_acc(x3 - m);
    float s = (e0 + e1) + (e2 + e3);
    #pragma unroll
    for (int o = 16; o; o >>= 1)
        s += __shfl_xor_sync(0xffffffffu, s, o);
    if ((t & 31) == 0) red[4 + (t >> 5)] = s;
    __syncthreads();
    s = (red[4] + red[5]) + (red[6] + red[7]);

    float inv = 1.0f / s;
    size_t base = (size_t)blockIdx.x * 512;
    float pv[4] = {e0 * inv, e1 * inv, e2 * inv, e3 * inv};
    int col[4]  = {t, t + 128, t + 256, t + 384};
    #pragma unroll
    for (int i = 0; i < 4; i++) {
        fp16 b0, b1, b2;
        split3h(pv[i], b0, b1, b2);
        P[base + col[i]]                 = b0;
        P[PLANE_P + base + col[i]]       = b1;
        P[2 * PLANE_P + base + col[i]]   = b2;
    }
}

// ---------------------------------------------------------------------------
// Deterministic 2-stage BatchNorm stats.
// ---------------------------------------------------------------------------
__global__ __launch_bounds__(256)
void bn_stage1(const float* __restrict__ WX, float* __restrict__ psum,
               float* __restrict__ psq)
{
    const int blk = blockIdx.x;
    const int t   = threadIdx.x;
    const float* base = WX + (size_t)blk * 32 * HH;
    float s0 = 0.f, s1 = 0.f, q0 = 0.f, q1 = 0.f;
    for (int r = 0; r < 32; r++) {
        float a0 = base[(size_t)r * HH + t];
        float a1 = base[(size_t)r * HH + t + 256];
        s0 += a0; q0 = fmaf(a0, a0, q0);
        s1 += a1; q1 = fmaf(a1, a1, q1);
    }
    psum[(size_t)blk * HH + t]       = s0;
    psum[(size_t)blk * HH + t + 256] = s1;
    psq [(size_t)blk * HH + t]       = q0;
    psq [(size_t)blk * HH + t + 256] = q1;
}

__global__ __launch_bounds__(512)
void bn_stage2(const float* __restrict__ psum, const float* __restrict__ psq,
               float* __restrict__ sum, float* __restrict__ sq)
{
    const int h = threadIdx.x;
    float s = 0.f, q = 0.f;
    for (int i = 0; i < 256; i++) {
        s += psum[(size_t)i * HH + h];
        q += psq [(size_t)i * HH + h];
    }
    sum[h] = s;
    sq[h]  = q;
}

// ---------------------------------------------------------------------------
// Fused BN + LIF scan.
// ---------------------------------------------------------------------------
__global__ __launch_bounds__(256)
void lif_kernel(const float* __restrict__ WX,
                const float* __restrict__ sum, const float* __restrict__ sq,
                const float* __restrict__ gamma, const float* __restrict__ beta,
                float* __restrict__ out)
{
    const int g = blockIdx.x * blockDim.x + threadIdx.x;
    const int b = g >> 9;
    const int h = g & 511;

    const float inv_n = 1.0f / (float)BT;
    float mu  = sum[h] * inv_n;
    float var = fmaf(-mu, mu, sq[h] * inv_n);
    float scale = gamma[h] * __frsqrt_rn(var + 1e-5f);
    float shift = fmaf(-mu, scale, beta[h]);

    const float* wp = WX  + (size_t)b * TT * HH + h;
    float*       op = out + (size_t)b * TT * HH + h;

    float u = 0.0f;
    for (int t = 0; t < TT; t += 8) {
        float w[8];
        #pragma unroll
        for (int j = 0; j < 8; j++)
            w[j] = wp[(size_t)(t + j) * HH];
        #pragma unroll
        for (int j = 0; j < 8; j++) {
            u = fmaf(0.5f, u, fmaf(w[j], scale, shift));
            float s = (u > 1.0f) ? 1.0f : 0.0f;
            op[(size_t)(t + j) * HH] = s;
            u = (1.0f - s) * u;
        }
    }
}

// ---------------------------------------------------------------------------
// Launch
// ---------------------------------------------------------------------------
extern "C" void kernel_launch(void* const* d_in, const int* in_sizes, int n_in,
                              void* d_out, int out_size)
{
    const float* v     = (const float*)d_in[0];
    const float* a     = (const float*)d_in[1];
    const float* Wq    = (const float*)d_in[2];
    const float* Wk    = (const float*)d_in[3];
    const float* Wv    = (const float*)d_in[4];
    const float* Wo    = (const float*)d_in[5];
    const float* W     = (const float*)d_in[6];
    const float* gamma = (const float*)d_in[7];
    const float* beta  = (const float*)d_in[8];
    float* out = (float*)d_out;

    float *Sf, *Vf, *WXf, *PSU, *PSQ, *SM, *SQ;
    fp16 *vS, *aS, *QS, *KS, *OS, *XS, *PS, *VtS, *WqT, *WkT, *WvT, *WoT, *WT;
    cudaGetSymbolAddress((void**)&Sf,  g_S);
    cudaGetSymbolAddress((void**)&Vf,  g_Vf);
    cudaGetSymbolAddress((void**)&WXf, g_WX);
    cudaGetSymbolAddress((void**)&PSU, g_psum);
    cudaGetSymbolAddress((void**)&PSQ, g_psq);
    cudaGetSymbolAddress((void**)&SM,  g_sum);
    cudaGetSymbolAddress((void**)&SQ,  g_sq);
    cudaGetSymbolAddress((void**)&vS,  g_vS);
    cudaGetSymbolAddress((void**)&aS,  g_aS);
    cudaGetSymbolAddress((void**)&QS,  g_QS);
    cudaGetSymbolAddress((void**)&KS,  g_KS);
    cudaGetSymbolAddress((void**)&OS,  g_OS);
    cudaGetSymbolAddress((void**)&XS,  g_XS);
    cudaGetSymbolAddress((void**)&PS,  g_PS);
    cudaGetSymbolAddress((void**)&VtS, g_VtS);
    cudaGetSymbolAddress((void**)&WqT, g_WqT);
    cudaGetSymbolAddress((void**)&WkT, g_WkT);
    cudaGetSymbolAddress((void**)&WvT, g_WvT);
    cudaGetSymbolAddress((void**)&WoT, g_WoT);
    cudaGetSymbolAddress((void**)&WT,  g_WT);

    const long T2 = (long)TT * TT;     // 262144
    const long TH = (long)TT * HH;     // 262144

    // smem: 2 stages x (3 A planes 128x80B + 3 B planes 64x80B) = 92,160 B
    const int SMB = 2 * (3 * 128 * 80 + 3 * 64 * 80);
    cudaFuncSetAttribute(tgemm<0,false>, cudaFuncAttributeMaxDynamicSharedMemorySize, SMB);
    cudaFuncSetAttribute(tgemm<1,false>, cudaFuncAttributeMaxDynamicSharedMemorySize, SMB);
    cudaFuncSetAttribute(tgemm<1,true>,  cudaFuncAttributeMaxDynamicSharedMemorySize, SMB);

    // 0) input splits
    split_act<<<4096, 256>>>(v, vS, PLANE_ACT);
    split_act<<<4096, 256>>>(a, aS, PLANE_ACT);
    W5 w5 = {{Wq, Wk, Wv, Wo, W}, {WqT, WkT, WvT, WoT, WT}};
    wsplit<<<dim3(16, 16, 5), 256>>>(w5);

    // 1-3) projections: Q = v@Wq (split), K = a@Wk (split), V = a@Wv (fp32)
    tgemm<1,false><<<dim3(8,64,1), 256, SMB>>>(
        vS, PLANE_ACT, WqT, PLANE_W, nullptr, QS, PLANE_ACT, nullptr,
        512, 512, 512, 512, 1.0f, 1, 0,0,0,0,0,0);
    tgemm<1,false><<<dim3(8,64,1), 256, SMB>>>(
        aS, PLANE_ACT, WkT, PLANE_W, nullptr, KS, PLANE_ACT, nullptr,
        512, 512, 512, 512, 1.0f, 1, 0,0,0,0,0,0);
    tgemm<0,false><<<dim3(8,64,1), 256, SMB>>>(
        aS, PLANE_ACT, WvT, PLANE_W, Vf, nullptr, 0, nullptr,
        512, 512, 512, 512, 1.0f, 1, 0,0,0,0,0,0);
    vtrans_split<<<dim3(16,16,16), 256>>>(Vf, VtS);

    // 4) scores S = (1/8) Q K^T  (fp32)
    tgemm<0,false><<<dim3(8,4,NBH), 256, SMB>>>(
        QS, PLANE_ACT, KS, PLANE_ACT, Sf, nullptr, 0, nullptr,
        64, 512, 512, 512, 0.125f,
        NH, TH, 64, TH, 64, (long)NH * T2, T2);

    // 5) softmax + split -> P planes
    softmax_split<<<NBH * TT, 128>>>(Sf, PS);

    // 6) O = P @ V  (split out)
    tgemm<1,false><<<dim3(1,4,NBH), 256, SMB>>>(
        PS, PLANE_P, VtS, PLANE_VT, nullptr, OS, PLANE_ACT, nullptr,
        512, 512, 512, 512, 1.0f,
        NH, (long)NH * T2, T2, (long)HH * TT, (long)64 * TT, TH, 64);

    // 7) X = O @ Wo + a  (split out)
    tgemm<1,true><<<dim3(8,64,1), 256, SMB>>>(
        OS, PLANE_ACT, WoT, PLANE_W, nullptr, XS, PLANE_ACT, a,
        512, 512, 512, 512, 1.0f, 1, 0,0,0,0,0,0);

    // 8) WX = X @ W  (fp32)
    tgemm<0,false><<<dim3(8,64,1), 256, SMB>>>(
        XS, PLANE_ACT, WT, PLANE_W, WXf, nullptr, 0, nullptr,
        512, 512, 512, 512, 1.0f, 1, 0,0,0,0,0,0);

    // 9-10) BN stats (deterministic)
    bn_stage1<<<256, 256>>>(WXf, PSU, PSQ);
    bn_stage2<<<1, 512>>>(PSU, PSQ, SM, SQ);

    // 11) fused BN + LIF
    lif_kernel<<<32, 256>>>(WXf, SM, SQ, gamma, beta, out);
}

// round 12
// speedup vs baseline: 1.5059x; 1.5059x over previous
#include <cuda_runtime.h>
#include <cuda_fp16.h>
#include <cstdint>

// Problem dims (fixed by the reference)
#define BB   16
#define TT   512
#define HH   512
#define BT   (BB*TT)        // 8192
#define NH   8
#define DH   64
#define NBH  (BB*NH)        // 128

typedef __half fp16;

#define PLANE_ACT ((size_t)BT*HH)          // 4,194,304
#define PLANE_P   ((size_t)NBH*TT*TT)      // 33,554,432
#define PLANE_VT  ((size_t)BB*HH*TT)       // 4,194,304
#define PLANE_W   ((size_t)HH*HH)          // 262,144

// ---------------------------------------------------------------------------
// Scratch (static device globals — no allocation)
// ---------------------------------------------------------------------------
__device__ float g_S  [(size_t)NBH*TT*TT];   // fp32 scores
__device__ float g_WX [PLANE_ACT];           // fp32 LIF drive
__device__ float g_psum[256*HH];
__device__ float g_psq [256*HH];
__device__ float g_sum[HH];
__device__ float g_sq [HH];

__device__ fp16 g_vS [3*PLANE_ACT];
__device__ fp16 g_aS [3*PLANE_ACT];
__device__ fp16 g_QS [3*PLANE_ACT];
__device__ fp16 g_KS [3*PLANE_ACT];
__device__ fp16 g_VS [3*PLANE_ACT];
__device__ fp16 g_OS [3*PLANE_ACT];
__device__ fp16 g_XS [3*PLANE_ACT];
__device__ fp16 g_PS [3*PLANE_P];
__device__ fp16 g_VtS[3*PLANE_VT];
__device__ fp16 g_WqT[3*PLANE_W];
__device__ fp16 g_WkT[3*PLANE_W];
__device__ fp16 g_WvT[3*PLANE_W];
__device__ fp16 g_WoT[3*PLANE_W];
__device__ fp16 g_WT [3*PLANE_W];

struct Sel3 { const fp16* A[3]; fp16* C[3]; };

// ---------------------------------------------------------------------------
// Helpers
// ---------------------------------------------------------------------------
__device__ __forceinline__ uint32_t smem_u32(const void* p) {
    uint32_t a;
    asm("{ .reg .u64 t; cvta.to.shared.u64 t, %1; cvt.u32.u64 %0, t; }"
        : "=r"(a) : "l"(p));
    return a;
}
__device__ __forceinline__ void cpa16(uint32_t d, const void* s) {
    asm volatile("cp.async.ca.shared.global [%0], [%1], 16;" :: "r"(d), "l"(s));
}
#define CP_COMMIT() asm volatile("cp.async.commit_group;" ::: "memory")
#define CP_WAIT1()  asm volatile("cp.async.wait_group 1;" ::: "memory")

__device__ __forceinline__ void ldsm4(uint32_t& r0, uint32_t& r1,
                                      uint32_t& r2, uint32_t& r3, uint32_t a) {
    asm volatile("ldmatrix.sync.aligned.m8n8.x4.shared.b16 {%0,%1,%2,%3}, [%4];"
                 : "=r"(r0), "=r"(r1), "=r"(r2), "=r"(r3) : "r"(a));
}
__device__ __forceinline__ void mma16816(float* c, const uint32_t* a,
                                         uint32_t b0, uint32_t b1) {
    asm volatile(
        "mma.sync.aligned.m16n8k16.row.col.f32.f16.f16.f32 "
        "{%0,%1,%2,%3}, {%4,%5,%6,%7}, {%8,%9}, {%0,%1,%2,%3};"
        : "+f"(c[0]), "+f"(c[1]), "+f"(c[2]), "+f"(c[3])
        : "r"(a[0]), "r"(a[1]), "r"(a[2]), "r"(a[3]), "r"(b0), "r"(b1));
}

// 3-way fp16 split (33 mantissa bits; residual ~2^-33 relative)
__device__ __forceinline__ void split3h(float x, fp16& h0, fp16& h1, fp16& h2) {
    h0 = __float2half_rn(x);
    float r = x - __half2float(h0);
    h1 = __float2half_rn(r);
    r -= __half2float(h1);
    h2 = __float2half_rn(r);
}

// ---------------------------------------------------------------------------
// Accurate expf, immune to --use_fast_math.
// ---------------------------------------------------------------------------
__device__ __forceinline__ float exp_acc(float x) {
    x = fmaxf(x, -87.0f);
    float z = x * 1.44269504088896341f;
    float n = rintf(z);
    float f = fmaf(n, -0.693145751953125f, x);
    f = fmaf(n, -1.428606765330187e-06f, f);
    float p = 1.9841269841e-4f;
    p = fmaf(p, f, 1.3888888889e-3f);
    p = fmaf(p, f, 8.3333333333e-3f);
    p = fmaf(p, f, 4.1666666667e-2f);
    p = fmaf(p, f, 1.6666666667e-1f);
    p = fmaf(p, f, 0.5f);
    p = fmaf(p, f, 1.0f);
    p = fmaf(p, f, 1.0f);
    int ni = (int)n;
    float sc = __int_as_float((ni + 127) << 23);
    return p * sc;
}

// ---------------------------------------------------------------------------
// HMMA split-fp16 GEMM (mma.sync m16n8k16 f16).
//   6 products {00,01,10,11,02,20}; two accumulator banks (main (0,0) bank
//   plain fp32 accumulation — proven flip-free; small-products bank separate).
//   Warp tile fixed 32x64 (best measured config). MW x NW warp grid:
//     (4,2): BM=128 BN=128  |  (8,1): BM=256 BN=64 (P@V shape)
//   BK=32 chunks, 256 thr, 2-stage cp.async, B-fragment double buffering.
//   EPI: 0 = fp32 C;  1 = 3 fp16 split planes (+ optional fp32 residual).
//   SEL: blockIdx.z selects (A, C) from Sel3 (merged Q/K/V projections).
// ---------------------------------------------------------------------------
template<int MW, int NW, int EPI, bool RESID, bool SEL>
__global__ __launch_bounds__(256)
void tgemm(const fp16* __restrict__ A, long planeA,
           const fp16* __restrict__ B, long planeB,
           float* __restrict__ Cf, fp16* __restrict__ Cs, long planeC,
           const float* __restrict__ R,
           int K, int lda, int ldb, int ldc, float alpha,
           int heads, long sAb, long sAh, long sBb, long sBh,
           long sCb, long sCh, Sel3 sel)
{
    constexpr int BM  = MW * 32;
    constexpr int BN  = NW * 64;
    constexpr int APL = BM * 80;           // bytes per A plane (80B pitch rows)
    constexpr int BPL = BN * 80;
    constexpr int ASET = 3 * APL;
    constexpr int STAGE = ASET + 3 * BPL;
    constexpr int AIT = (3 * BM * 4) / 256;    // A cp.async iters
    constexpr int BIT = (3 * BN * 4) / 256;    // B cp.async iters

    extern __shared__ __align__(16) char smem[];
    const uint32_t sb = smem_u32(smem);

    const int tid = threadIdx.x, wid = tid >> 5, lane = tid & 31;
    const int wm = wid % MW, wn = wid / MW;
    const int z = blockIdx.z;
    size_t coff;
    if (SEL) {
        A = sel.A[z];
        Cs = sel.C[z];
        coff = 0;
    } else {
        const int zb = z / heads, zh = z - zb * heads;
        A += (size_t)zb * sAb + (size_t)zh * sAh;
        B += (size_t)zb * sBb + (size_t)zh * sBh;
        coff = (size_t)zb * sCb + (size_t)zh * sCh;
    }
    const int m0 = blockIdx.y * BM, n0 = blockIdx.x * BN;
    const int nch = K >> 5;

    auto loadStageG = [&](int ch) {
        if (ch < nch) {
            const int k0 = ch * 32;
            const uint32_t ab = sb + (ch & 1) * STAGE;
            #pragma unroll
            for (int it = 0; it < AIT; it++) {
                int idx = tid + it * 256;
                int p = idx / (BM * 4), rem = idx % (BM * 4);
                int r = rem >> 2, c = rem & 3;
                cpa16(ab + p * APL + r * 80 + c * 16,
                      A + (size_t)p * planeA + (size_t)(m0 + r) * lda + k0 + c * 8);
            }
            const uint32_t bb = ab + ASET;
            #pragma unroll
            for (int it = 0; it < BIT; it++) {
                int idx = tid + it * 256;
                int p = idx / (BN * 4), rem = idx % (BN * 4);
                int r = rem >> 2, c = rem & 3;
                cpa16(bb + p * BPL + r * 80 + c * 16,
                      B + (size_t)p * planeB + (size_t)(n0 + r) * ldb + k0 + c * 8);
            }
        }
        CP_COMMIT();
    };

    float accA[2][8][4], accB[2][8][4];
    #pragma unroll
    for (int i = 0; i < 2; i++)
        #pragma unroll
        for (int j = 0; j < 8; j++)
            #pragma unroll
            for (int q = 0; q < 4; q++) { accA[i][j][q] = 0.f; accB[i][j][q] = 0.f; }

    loadStageG(0);

    const int lrow = lane & 15;
    const int lcol = (lane >> 4) << 4;

    for (int ch = 0; ch < nch; ch++) {
        loadStageG(ch + 1);
        CP_WAIT1();
        __syncthreads();

        const uint32_t ab = sb + (ch & 1) * STAGE;
        const uint32_t bb = ab + ASET;
        const uint32_t arow = (wm * 32 + lrow) * 80 + lcol;
        const uint32_t brow = (wn * 64 + lrow) * 80 + lcol;

        #pragma unroll
        for (int ks = 0; ks < 2; ks++) {
            // prefetch B fragments for pb=0 FIRST (hides latency under af loads)
            uint32_t bf[2][4][4];
            #pragma unroll
            for (int tp = 0; tp < 4; tp++)
                ldsm4(bf[0][tp][0], bf[0][tp][1], bf[0][tp][2], bf[0][tp][3],
                      bb + brow + tp * (16 * 80) + ks * 32);

            uint32_t af[3][2][4];
            #pragma unroll
            for (int pa = 0; pa < 3; pa++)
                #pragma unroll
                for (int mt = 0; mt < 2; mt++)
                    ldsm4(af[pa][mt][0], af[pa][mt][1], af[pa][mt][2], af[pa][mt][3],
                          ab + pa * APL + arow + mt * (16 * 80) + ks * 32);

            #pragma unroll
            for (int pb = 0; pb < 3; pb++) {
                // prefetch next plane's B fragments before this plane's MMAs
                if (pb < 2) {
                    #pragma unroll
                    for (int tp = 0; tp < 4; tp++)
                        ldsm4(bf[(pb + 1) & 1][tp][0], bf[(pb + 1) & 1][tp][1],
                              bf[(pb + 1) & 1][tp][2], bf[(pb + 1) & 1][tp][3],
                              bb + (pb + 1) * BPL + brow + tp * (16 * 80) + ks * 32);
                }
                const int cur = pb & 1;
                #pragma unroll
                for (int pa = 0; pa < 3 - pb; pa++) {
                    #pragma unroll
                    for (int mt = 0; mt < 2; mt++)
                        #pragma unroll
                        for (int tp = 0; tp < 4; tp++) {
                            float* c0 = (pa == 0 && pb == 0)
                                      ? accA[mt][2*tp]   : accB[mt][2*tp];
                            float* c1 = (pa == 0 && pb == 0)
                                      ? accA[mt][2*tp+1] : accB[mt][2*tp+1];
                            mma16816(c0, af[pa][mt], bf[cur][tp][0], bf[cur][tp][2]);
                            mma16816(c1, af[pa][mt], bf[cur][tp][1], bf[cur][tp][3]);
                        }
                }
            }
        }
        __syncthreads();
    }

    // ---- epilogue: res = accA + accB
    Cf += coff; Cs += coff;
    if (RESID) R += coff;
    const int quad = lane >> 2, tq = lane & 3;
    #pragma unroll
    for (int mt = 0; mt < 2; mt++) {
        #pragma unroll
        for (int nt = 0; nt < 8; nt++) {
            const int col = n0 + wn * 64 + nt * 8 + tq * 2;
            #pragma unroll
            for (int h = 0; h < 2; h++) {
                const int row = m0 + wm * 32 + mt * 16 + quad + h * 8;
                float x0 = (accA[mt][nt][2*h]   + accB[mt][nt][2*h])   * alpha;
                float x1 = (accA[mt][nt][2*h+1] + accB[mt][nt][2*h+1]) * alpha;
                const size_t off = (size_t)row * ldc + col;
                if (RESID) {
                    float2 rv = *reinterpret_cast<const float2*>(R + off);
                    x0 += rv.x; x1 += rv.y;
                }
                if (EPI == 0) {
                    *reinterpret_cast<float2*>(Cf + off) = make_float2(x0, x1);
                } else {
                    fp16 a0, a1, a2, b0, b1, b2;
                    split3h(x0, a0, a1, a2);
                    split3h(x1, b0, b1, b2);
                    *reinterpret_cast<__half2*>(Cs + off)
                        = __halves2half2(a0, b0);
                    *reinterpret_cast<__half2*>(Cs + planeC + off)
                        = __halves2half2(a1, b1);
                    *reinterpret_cast<__half2*>(Cs + 2 * planeC + off)
                        = __halves2half2(a2, b2);
                }
            }
        }
    }
}

// ---------------------------------------------------------------------------
// fp32 -> 3 fp16 planes (elementwise, for inputs v and a)
// ---------------------------------------------------------------------------
__global__ __launch_bounds__(256)
void split_act(const float* __restrict__ src, fp16* __restrict__ dst, long plane)
{
    size_t i = (size_t)blockIdx.x * 256 + threadIdx.x;     // float4 index
    float4 x = reinterpret_cast<const float4*>(src)[i];
    fp16 p[3][4];
    split3h(x.x, p[0][0], p[1][0], p[2][0]);
    split3h(x.y, p[0][1], p[1][1], p[2][1]);
    split3h(x.z, p[0][2], p[1][2], p[2][2]);
    split3h(x.w, p[0][3], p[1][3], p[2][3]);
    #pragma unroll
    for (int q = 0; q < 3; q++) {
        __half2* d = reinterpret_cast<__half2*>(dst + q * plane) + i * 2;
        d[0] = __halves2half2(p[q][0], p[q][1]);
        d[1] = __halves2half2(p[q][2], p[q][3]);
    }
}

// ---------------------------------------------------------------------------
// transpose + split of the five 512x512 weights (B operands want [N,K])
// ---------------------------------------------------------------------------
struct W5 { const float* s[5]; fp16* d[5]; };

__global__ __launch_bounds__(256)
void wsplit(W5 args)
{
    __shared__ float t[32][33];
    const float* S = args.s[blockIdx.z];
    fp16* D = args.d[blockIdx.z];
    int tx = threadIdx.x & 31, ty = threadIdx.x >> 5;
    int c0 = blockIdx.x * 32, r0 = blockIdx.y * 32;
    #pragma unroll
    for (int i = 0; i < 4; i++)
        t[ty + i * 8][tx] = S[(size_t)(r0 + ty + i * 8) * 512 + c0 + tx];
    __syncthreads();
    #pragma unroll
    for (int i = 0; i < 4; i++) {
        int no = c0 + ty + i * 8;
        int ko = r0 + tx;
        fp16 b0, b1, b2;
        split3h(t[tx][ty + i * 8], b0, b1, b2);
        D[(size_t)no * 512 + ko]                 = b0;
        D[PLANE_W + (size_t)no * 512 + ko]       = b1;
        D[2 * PLANE_W + (size_t)no * 512 + ko]   = b2;
    }
}

// ---------------------------------------------------------------------------
// V planes [b,t,d] -> Vt planes [b,d,t] (reconstruct fp32, transpose, split)
// ---------------------------------------------------------------------------
__global__ __launch_bounds__(256)
void vtrans_split(const fp16* __restrict__ VS, fp16* __restrict__ D)
{
    __shared__ float t[32][33];
    int b = blockIdx.z;
    fp16* Db = D + (size_t)b * HH * TT;
    int tx = threadIdx.x & 31, ty = threadIdx.x >> 5;
    int c0 = blockIdx.x * 32, r0 = blockIdx.y * 32;    // c = d, r = t
    #pragma unroll
    for (int i = 0; i < 4; i++) {
        size_t idx = (size_t)(b * TT + r0 + ty + i * 8) * 512 + c0 + tx;
        float x = __half2float(VS[idx])
                + __half2float(VS[PLANE_ACT + idx])
                + __half2float(VS[2 * PLANE_ACT + idx]);
        t[ty + i * 8][tx] = x;
    }
    __syncthreads();
    #pragma unroll
    for (int i = 0; i < 4; i++) {
        int dd = c0 + ty + i * 8;
        int tt = r0 + tx;
        fp16 b0, b1, b2;
        split3h(t[tx][ty + i * 8], b0, b1, b2);
        Db[(size_t)dd * 512 + tt]                  = b0;
        Db[PLANE_VT + (size_t)dd * 512 + tt]       = b1;
        Db[2 * PLANE_VT + (size_t)dd * 512 + tt]   = b2;
    }
}

// ---------------------------------------------------------------------------
// Row softmax (512) fused with 3-way split output.
// ---------------------------------------------------------------------------
__global__ __launch_bounds__(128)
void softmax_split(const float* __restrict__ S, fp16* __restrict__ P)
{
    __shared__ float red[8];
    const int t = threadIdx.x;
    const float* p = S + (size_t)blockIdx.x * 512;

    float x0 = p[t], x1 = p[t + 128], x2 = p[t + 256], x3 = p[t + 384];
    float m = fmaxf(fmaxf(x0, x1), fmaxf(x2, x3));
    #pragma unroll
    for (int o = 16; o; o >>= 1)
        m = fmaxf(m, __shfl_xor_sync(0xffffffffu, m, o));
    if ((t & 31) == 0) red[t >> 5] = m;
    __syncthreads();
    m = fmaxf(fmaxf(red[0], red[1]), fmaxf(red[2], red[3]));

    float e0 = exp_acc(x0 - m), e1 = exp_acc(x1 - m);
    float e2 = exp_acc(x2 - m), e3 = exp_acc(x3 - m);
    float s = (e0 + e1) + (e2 + e3);
    #pragma unroll
    for (int o = 16; o; o >>= 1)
        s += __shfl_xor_sync(0xffffffffu, s, o);
    if ((t & 31) == 0) red[4 + (t >> 5)] = s;
    __syncthreads();
    s = (red[4] + red[5]) + (red[6] + red[7]);

    float inv = 1.0f / s;
    size_t base = (size_t)blockIdx.x * 512;
    float pv[4] = {e0 * inv, e1 * inv, e2 * inv, e3 * inv};
    int col[4]  = {t, t + 128, t + 256, t + 384};
    #pragma unroll
    for (int i = 0; i < 4; i++) {
        fp16 b0, b1, b2;
        split3h(pv[i], b0, b1, b2);
        P[base + col[i]]                 = b0;
        P[PLANE_P + base + col[i]]       = b1;
        P[2 * PLANE_P + base + col[i]]   = b2;
    }
}

// ---------------------------------------------------------------------------
// Deterministic 2-stage BatchNorm stats.
// ---------------------------------------------------------------------------
__global__ __launch_bounds__(256)
void bn_stage1(const float* __restrict__ WX, float* __restrict__ psum,
               float* __restrict__ psq)
{
    const int blk = blockIdx.x;
    const int t   = threadIdx.x;
    const float* base = WX + (size_t)blk * 32 * HH;
    float s0 = 0.f, s1 = 0.f, q0 = 0.f, q1 = 0.f;
    for (int r = 0; r < 32; r++) {
        float a0 = base[(size_t)r * HH + t];
        float a1 = base[(size_t)r * HH + t + 256];
        s0 += a0; q0 = fmaf(a0, a0, q0);
        s1 += a1; q1 = fmaf(a1, a1, q1);
    }
    psum[(size_t)blk * HH + t]       = s0;
    psum[(size_t)blk * HH + t + 256] = s1;
    psq [(size_t)blk * HH + t]       = q0;
    psq [(size_t)blk * HH + t + 256] = q1;
}

__global__ __launch_bounds__(512)
void bn_stage2(const float* __restrict__ psum, const float* __restrict__ psq,
               float* __restrict__ sum, float* __restrict__ sq)
{
    const int h = threadIdx.x;
    float s = 0.f, q = 0.f;
    for (int i = 0; i < 256; i++) {
        s += psum[(size_t)i * HH + h];
        q += psq [(size_t)i * HH + h];
    }
    sum[h] = s;
    sq[h]  = q;
}

// ---------------------------------------------------------------------------
// Fused BN + LIF scan.
// ---------------------------------------------------------------------------
__global__ __launch_bounds__(256)
void lif_kernel(const float* __restrict__ WX,
                const float* __restrict__ sum, const float* __restrict__ sq,
                const float* __restrict__ gamma, const float* __restrict__ beta,
                float* __restrict__ out)
{
    const int g = blockIdx.x * blockDim.x + threadIdx.x;
    const int b = g >> 9;
    const int h = g & 511;

    const float inv_n = 1.0f / (float)BT;
    float mu  = sum[h] * inv_n;
    float var = fmaf(-mu, mu, sq[h] * inv_n);
    float scale = gamma[h] * __frsqrt_rn(var + 1e-5f);
    float shift = fmaf(-mu, scale, beta[h]);

    const float* wp = WX  + (size_t)b * TT * HH + h;
    float*       op = out + (size_t)b * TT * HH + h;

    float u = 0.0f;
    for (int t = 0; t < TT; t += 8) {
        float w[8];
        #pragma unroll
        for (int j = 0; j < 8; j++)
            w[j] = wp[(size_t)(t + j) * HH];
        #pragma unroll
        for (int j = 0; j < 8; j++) {
            u = fmaf(0.5f, u, fmaf(w[j], scale, shift));
            float s = (u > 1.0f) ? 1.0f : 0.0f;
            op[(size_t)(t + j) * HH] = s;
            u = (1.0f - s) * u;
        }
    }
}

// ---------------------------------------------------------------------------
// Launch
// ---------------------------------------------------------------------------
extern "C" void kernel_launch(void* const* d_in, const int* in_sizes, int n_in,
                              void* d_out, int out_size)
{
    const float* v     = (const float*)d_in[0];
    const float* a     = (const float*)d_in[1];
    const float* Wq    = (const float*)d_in[2];
    const float* Wk    = (const float*)d_in[3];
    const float* Wv    = (const float*)d_in[4];
    const float* Wo    = (const float*)d_in[5];
    const float* W     = (const float*)d_in[6];
    const float* gamma = (const float*)d_in[7];
    const float* beta  = (const float*)d_in[8];
    float* out = (float*)d_out;

    float *Sf, *WXf, *PSU, *PSQ, *SM, *SQ;
    fp16 *vS, *aS, *QS, *KS, *VS, *OS, *XS, *PS, *VtS, *WqT, *WkT, *WvT, *WoT, *WT;
    cudaGetSymbolAddress((void**)&Sf,  g_S);
    cudaGetSymbolAddress((void**)&WXf, g_WX);
    cudaGetSymbolAddress((void**)&PSU, g_psum);
    cudaGetSymbolAddress((void**)&PSQ, g_psq);
    cudaGetSymbolAddress((void**)&SM,  g_sum);
    cudaGetSymbolAddress((void**)&SQ,  g_sq);
    cudaGetSymbolAddress((void**)&vS,  g_vS);
    cudaGetSymbolAddress((void**)&aS,  g_aS);
    cudaGetSymbolAddress((void**)&QS,  g_QS);
    cudaGetSymbolAddress((void**)&KS,  g_KS);
    cudaGetSymbolAddress((void**)&VS,  g_VS);
    cudaGetSymbolAddress((void**)&OS,  g_OS);
    cudaGetSymbolAddress((void**)&XS,  g_XS);
    cudaGetSymbolAddress((void**)&PS,  g_PS);
    cudaGetSymbolAddress((void**)&VtS, g_VtS);
    cudaGetSymbolAddress((void**)&WqT, g_WqT);
    cudaGetSymbolAddress((void**)&WkT, g_WkT);
    cudaGetSymbolAddress((void**)&WvT, g_WvT);
    cudaGetSymbolAddress((void**)&WoT, g_WoT);
    cudaGetSymbolAddress((void**)&WT,  g_WT);

    const long T2 = (long)TT * TT;     // 262144
    const long TH = (long)TT * HH;     // 262144
    Sel3 none = {};

    // smem: 2 stages x 3 planes x (BM + BN) x 80 B
    const int SM_128_128 = 2 * 3 * (128 + 128) * 80;   // 122,880 B
    const int SM_256_64  = 2 * 3 * (256 + 64)  * 80;   // 153,600 B
    cudaFuncSetAttribute((const void*)tgemm<4,2,0,false,false>,
        cudaFuncAttributeMaxDynamicSharedMemorySize, SM_128_128);
    cudaFuncSetAttribute((const void*)tgemm<4,2,1,false,false>,
        cudaFuncAttributeMaxDynamicSharedMemorySize, SM_128_128);
    cudaFuncSetAttribute((const void*)tgemm<4,2,1,true,false>,
        cudaFuncAttributeMaxDynamicSharedMemorySize, SM_128_128);
    cudaFuncSetAttribute((const void*)tgemm<4,2,1,false,true>,
        cudaFuncAttributeMaxDynamicSharedMemorySize, SM_128_128);
    cudaFuncSetAttribute((const void*)tgemm<8,1,1,false,false>,
        cudaFuncAttributeMaxDynamicSharedMemorySize, SM_256_64);

    // 0) input splits
    split_act<<<4096, 256>>>(v, vS, PLANE_ACT);
    split_act<<<4096, 256>>>(a, aS, PLANE_ACT);
    W5 w5 = {{Wq, Wk, Wv, Wo, W}, {WqT, WkT, WvT, WoT, WT}};
    wsplit<<<dim3(16, 16, 5), 256>>>(w5);

    // 1) merged projections: z=0: Q=v@Wq, z=1: K=a@Wk, z=2: V=a@Wv (all split)
    {
        Sel3 sel;
        sel.A[0] = vS; sel.A[1] = aS; sel.A[2] = aS;
        sel.C[0] = QS; sel.C[1] = KS; sel.C[2] = VS;
        // B differs per z too — but Wq/Wk/Wv are separate arrays; pass via
        // head-strided B: lay out as one batched pointer using sBh over the
        // contiguous g_WqT/g_WkT/g_WvT? Not contiguous — use heads trick off.
        // Instead: B selected by z via sBb with heads=1 requires contiguity.
        // Simplest correct: three B pointers can't be selected; so launch
        // with B = WqT and per-z offset computed from the fact that the three
        // weight arrays are consecutive __device__ globals is NOT guaranteed.
        // => fall back: keep SEL only for A/C and do 3 small launches for B.
        (void)sel;
    }
    // (B pointer can't be selected per z safely — use three launches)
    tgemm<4,2,1,false,false><<<dim3(4,64,1), 256, SM_128_128>>>(
        vS, PLANE_ACT, WqT, PLANE_W, nullptr, QS, PLANE_ACT, nullptr,
        512, 512, 512, 512, 1.0f, 1, 0,0,0,0,0,0, none);
    tgemm<4,2,1,false,false><<<dim3(4,64,1), 256, SM_128_128>>>(
        aS, PLANE_ACT, WkT, PLANE_W, nullptr, KS, PLANE_ACT, nullptr,
        512, 512, 512, 512, 1.0f, 1, 0,0,0,0,0,0, none);
    tgemm<4,2,1,false,false><<<dim3(4,64,1), 256, SM_128_128>>>(
        aS, PLANE_ACT, WvT, PLANE_W, nullptr, VS, PLANE_ACT, nullptr,
        512, 512, 512, 512, 1.0f, 1, 0,0,0,0,0,0, none);
    vtrans_split<<<dim3(16,16,16), 256>>>(VS, VtS);

    // 4) scores S = (1/8) Q K^T  (fp32)
    tgemm<4,2,0,false,false><<<dim3(4,4,NBH), 256, SM_128_128>>>(
        QS, PLANE_ACT, KS, PLANE_ACT, Sf, nullptr, 0, nullptr,
        64, 512, 512, 512, 0.125f,
        NH, TH, 64, TH, 64, (long)NH * T2, T2, none);

    // 5) softmax + split -> P planes
    softmax_split<<<NBH * TT, 128>>>(Sf, PS);

    // 6) O = P @ V  (split out) — BM=256, BN=64 shape (warp tile 32x64)
    tgemm<8,1,1,false,false><<<dim3(1,2,NBH), 256, SM_256_64>>>(
        PS, PLANE_P, VtS, PLANE_VT, nullptr, OS, PLANE_ACT, nullptr,
        512, 512, 512, 512, 1.0f,
        NH, (long)NH * T2, T2, (long)HH * TT, (long)64 * TT, TH, 64, none);

    // 7) X = O @ Wo + a  (split out)
    tgemm<4,2,1,true,false><<<dim3(4,64,1), 256, SM_128_128>>>(
        OS, PLANE_ACT, WoT, PLANE_W, nullptr, XS, PLANE_ACT, a,
        512, 512, 512, 512, 1.0f, 1, 0,0,0,0,0,0, none);

    // 8) WX = X @ W  (fp32)
    tgemm<4,2,0,false,false><<<dim3(4,64,1), 256, SM_128_128>>>(
        XS, PLANE_ACT, WT, PLANE_W, WXf, nullptr, 0, nullptr,
        512, 512, 512, 512, 1.0f, 1, 0,0,0,0,0,0, none);

    // 9-10) BN stats (deterministic)
    bn_stage1<<<256, 256>>>(WXf, PSU, PSQ);
    bn_stage2<<<1, 512>>>(PSU, PSQ, SM, SQ);

    // 11) fused BN + LIF
    lif_kernel<<<32, 256>>>(WXf, SM, SQ, gamma, beta, out);
}

// round 13
// speedup vs baseline: 1.6948x; 1.1255x over previous
#include <cuda_runtime.h>
#include <cstdint>

// Problem dims (fixed by the reference)
#define BB   16
#define TT   512
#define HH   512
#define BT   (BB*TT)        // 8192
#define NH   8
#define DH   64             // head dim
#define NBH  (BB*NH)        // 128 batched attention mats

typedef unsigned long long ull;

// ---------------------------------------------------------------------------
// Scratch (static device globals — no allocation)
// ---------------------------------------------------------------------------
__device__ float g_Q [(size_t)BT*HH];
__device__ float g_K [(size_t)BT*HH];
__device__ float g_V [(size_t)BT*HH];
__device__ float g_O [(size_t)BT*HH];
__device__ float g_X [(size_t)BT*HH];
__device__ float g_WX[(size_t)BT*HH];
__device__ float g_S [(size_t)NBH*TT*TT];     // 134 MB attention scores
__device__ float g_psum[(size_t)256*HH];
__device__ float g_psq [(size_t)256*HH];
__device__ float g_sum [HH];
__device__ float g_sq  [HH];

// ---------------------------------------------------------------------------
// f32x2 packed math (sm_103a FFMA2 — PTX-only)
// ---------------------------------------------------------------------------
__device__ __forceinline__ ull pack2(float x, float y) {
    ull r; asm("mov.b64 %0, {%1, %2};" : "=l"(r) : "f"(x), "f"(y)); return r;
}
__device__ __forceinline__ ull ffma2(ull a, ull b, ull c) {
    ull d; asm("fma.rn.f32x2 %0, %1, %2, %3;" : "=l"(d) : "l"(a), "l"(b), "l"(c));
    return d;
}
__device__ __forceinline__ void unpack2(ull v, float& x, float& y) {
    asm("mov.b64 {%0, %1}, %2;" : "=f"(x), "=f"(y) : "l"(v));
}
__device__ __forceinline__ uint32_t smem_u32(const void* p) {
    uint32_t a;
    asm("{ .reg .u64 t; cvta.to.shared.u64 t, %1; cvt.u32.u64 %0, t; }"
        : "=r"(a) : "l"(p));
    return a;
}
__device__ __forceinline__ void cpa16(uint32_t d, const void* s) {
    asm volatile("cp.async.ca.shared.global [%0], [%1], 16;" :: "r"(d), "l"(s));
}
#define CP_COMMIT() asm volatile("cp.async.commit_group;" ::: "memory")
#define CP_WAIT0()  asm volatile("cp.async.wait_group 0;" ::: "memory")

// ---------------------------------------------------------------------------
// Accurate expf, immune to --use_fast_math.
// ---------------------------------------------------------------------------
__device__ __forceinline__ float exp_acc(float x) {
    x = fmaxf(x, -87.0f);
    float z = x * 1.44269504088896341f;
    float n = rintf(z);
    float f = fmaf(n, -0.693145751953125f, x);
    f = fmaf(n, -1.428606765330187e-06f, f);
    float p = 1.9841269841e-4f;
    p = fmaf(p, f, 1.3888888889e-3f);
    p = fmaf(p, f, 8.3333333333e-3f);
    p = fmaf(p, f, 4.1666666667e-2f);
    p = fmaf(p, f, 1.6666666667e-1f);
    p = fmaf(p, f, 0.5f);
    p = fmaf(p, f, 1.0f);
    p = fmaf(p, f, 1.0f);
    int ni = (int)n;
    float sc = __int_as_float((ni + 127) << 23);
    return p * sc;
}

// ---------------------------------------------------------------------------
// fp32 GEMM, f32x2 accumulation (round-4 champion datapath) with BK=32
// K-tiles (half the barriers) and cp.async staging for non-transposed B.
//   BM=128, BK=32, 256 threads, TM=8, TN(8|4), 2 CTAs/SM, double-buffered.
// ---------------------------------------------------------------------------
template<int BN, int TN, bool TRANSB, bool RESID>
__global__ __launch_bounds__(256, 2)
void gemm5(const float* __restrict__ A, const float* __restrict__ Bm,
           float* __restrict__ C, const float* __restrict__ R,
           int M, int N, int K, int lda, int ldb, int ldc, float alpha,
           int heads, long sAb, long sAh, long sBb, long sBh,
           long sCb, long sCh)
{
    constexpr int BM = 128, BK = 32;
    constexpr int NPAIR = TN / 2;
    constexpr int BQ = BN / 4;
    constexpr int AS_ST = BM + 4;                 // 132
    constexpr int BS_ST = BN + 4;
    constexpr int ASZ = BK * AS_ST;
    constexpr int BSZ = BK * BS_ST;
    constexpr int BIT = (BK * BQ) / 256;          // cp.async iters for B

    extern __shared__ __align__(16) float sm[];   // [A0][A1][B0][B1]
    const uint32_t sbase = smem_u32(sm);

    const int z = blockIdx.z;
    const int zb = z / heads, zh = z % heads;
    A  += (size_t)zb * sAb + (size_t)zh * sAh;
    Bm += (size_t)zb * sBb + (size_t)zh * sBh;
    const size_t coff = (size_t)zb * sCb + (size_t)zh * sCh;

    const int tid = threadIdx.x;
    const int tx  = tid & 15;
    const int ty  = tid >> 4;
    const int m0  = blockIdx.y * BM;
    const int n0  = blockIdx.x * BN;

    const int ar = tid >> 3;             // 0..31 (row within 32-row group)
    const int aq = tid & 7;              // float4 index along K (0..7)

    float4 pa[4], pb[4];

    auto loadA = [&](int k0) {
        #pragma unroll
        for (int it = 0; it < 4; it++)
            pa[it] = *reinterpret_cast<const float4*>(
                &A[(size_t)(m0 + ar + it * 32) * lda + k0 + aq * 4]);
    };
    auto loadBT = [&](int k0) {          // TRANSB register path (BN==128)
        #pragma unroll
        for (int it = 0; it < 4; it++)
            pb[it] = *reinterpret_cast<const float4*>(
                &Bm[(size_t)(n0 + ar + it * 32) * ldb + k0 + aq * 4]);
    };
    auto cpB = [&](int k0, int buf) {    // non-TRANSB: cp.async straight in
        const uint32_t bbase = sbase + (2 * ASZ + buf * BSZ) * 4;
        #pragma unroll
        for (int it = 0; it < BIT; it++) {
            int idx = tid + it * 256;
            int kk = idx / BQ, nn = idx % BQ;
            cpa16(bbase + (kk * BS_ST + nn * 4) * 4,
                  &Bm[(size_t)(k0 + kk) * ldb + n0 + nn * 4]);
        }
    };
    auto storeA = [&](int buf) {
        float* As = sm + buf * ASZ;
        #pragma unroll
        for (int it = 0; it < 4; it++) {
            As[(aq*4 + 0) * AS_ST + ar + it*32] = pa[it].x;
            As[(aq*4 + 1) * AS_ST + ar + it*32] = pa[it].y;
            As[(aq*4 + 2) * AS_ST + ar + it*32] = pa[it].z;
            As[(aq*4 + 3) * AS_ST + ar + it*32] = pa[it].w;
        }
    };
    auto storeBT = [&](int buf) {
        float* Bs = sm + 2 * ASZ + buf * BSZ;
        #pragma unroll
        for (int it = 0; it < 4; it++) {
            Bs[(aq*4 + 0) * BS_ST + ar + it*32] = pb[it].x;
            Bs[(aq*4 + 1) * BS_ST + ar + it*32] = pb[it].y;
            Bs[(aq*4 + 2) * BS_ST + ar + it*32] = pb[it].z;
            Bs[(aq*4 + 3) * BS_ST + ar + it*32] = pb[it].w;
        }
    };

    ull acc[8][NPAIR];
    #pragma unroll
    for (int i = 0; i < 8; i++)
        #pragma unroll
        for (int j = 0; j < NPAIR; j++) acc[i][j] = 0ull;

    const int nch = K / BK;

    // prologue: stage chunk 0 into buf 0
    loadA(0);
    if (TRANSB) loadBT(0); else { cpB(0, 0); CP_COMMIT(); }
    storeA(0);
    if (TRANSB) storeBT(0); else CP_WAIT0();
    __syncthreads();
    int buf = 0;

    for (int ch = 0; ch < nch; ch++) {
        const int kn = (ch + 1) * BK;
        if (kn < K) {
            loadA(kn);
            if (TRANSB) loadBT(kn);
            else { cpB(kn, buf ^ 1); CP_COMMIT(); }
        }

        const float* As = sm + buf * ASZ;
        const float* Bs = sm + 2 * ASZ + buf * BSZ;

        #pragma unroll
        for (int kk = 0; kk < BK; kk++) {
            float4 av0 = *reinterpret_cast<const float4*>(&As[kk * AS_ST + ty * 4]);
            float4 av1 = *reinterpret_cast<const float4*>(&As[kk * AS_ST + ty * 4 + 64]);
            float a8[8] = {av0.x, av0.y, av0.z, av0.w,
                           av1.x, av1.y, av1.z, av1.w};
            ull aa[8];
            #pragma unroll
            for (int i = 0; i < 8; i++) aa[i] = pack2(a8[i], a8[i]);

            ull bp[NPAIR];
            {
                ulonglong2 b0 = *reinterpret_cast<const ulonglong2*>(&Bs[kk * BS_ST + tx * 4]);
                bp[0] = b0.x; bp[1] = b0.y;
                if (TN == 8) {
                    ulonglong2 b1 = *reinterpret_cast<const ulonglong2*>(&Bs[kk * BS_ST + tx * 4 + 64]);
                    bp[2] = b1.x; bp[3] = b1.y;
                }
            }
            #pragma unroll
            for (int i = 0; i < 8; i++)
                #pragma unroll
                for (int j = 0; j < NPAIR; j++)
                    acc[i][j] = ffma2(aa[i], bp[j], acc[i][j]);
        }

        if (kn < K) {
            storeA(buf ^ 1);
            if (TRANSB) storeBT(buf ^ 1); else CP_WAIT0();
            __syncthreads();
            buf ^= 1;
        }
    }

    // ---- epilogue
    C += coff;
    if (RESID) R += coff;
    #pragma unroll
    for (int i = 0; i < 8; i++) {
        int row = m0 + ty * 4 + (i & 3) + ((i >> 2) * 64);
        #pragma unroll
        for (int g = 0; g < TN / 4; g++) {
            size_t off = (size_t)row * ldc + n0 + tx * 4 + g * 64;
            float4 o;
            unpack2(acc[i][2*g + 0], o.x, o.y);
            unpack2(acc[i][2*g + 1], o.z, o.w);
            o.x *= alpha; o.y *= alpha; o.z *= alpha; o.w *= alpha;
            if (RESID) {
                float4 rv = *reinterpret_cast<const float4*>(&R[off]);
                o.x += rv.x; o.y += rv.y; o.z += rv.z; o.w += rv.w;
            }
            *reinterpret_cast<float4*>(&C[off]) = o;
        }
    }
}

// ---------------------------------------------------------------------------
// Row softmax over last dim (512). One block (128 thr) per row, in place.
// ---------------------------------------------------------------------------
__global__ __launch_bounds__(128)
void softmax_kernel(float* __restrict__ S)
{
    __shared__ float red[8];
    const int t = threadIdx.x;
    float* p = S + (size_t)blockIdx.x * 512;

    float x0 = p[t], x1 = p[t + 128], x2 = p[t + 256], x3 = p[t + 384];
    float m = fmaxf(fmaxf(x0, x1), fmaxf(x2, x3));
    #pragma unroll
    for (int o = 16; o; o >>= 1)
        m = fmaxf(m, __shfl_xor_sync(0xffffffffu, m, o));
    if ((t & 31) == 0) red[t >> 5] = m;
    __syncthreads();
    m = fmaxf(fmaxf(red[0], red[1]), fmaxf(red[2], red[3]));

    float e0 = exp_acc(x0 - m), e1 = exp_acc(x1 - m);
    float e2 = exp_acc(x2 - m), e3 = exp_acc(x3 - m);
    float s = (e0 + e1) + (e2 + e3);
    #pragma unroll
    for (int o = 16; o; o >>= 1)
        s += __shfl_xor_sync(0xffffffffu, s, o);
    if ((t & 31) == 0) red[4 + (t >> 5)] = s;
    __syncthreads();
    s = (red[4] + red[5]) + (red[6] + red[7]);

    float inv = 1.0f / s;
    p[t]       = e0 * inv;
    p[t + 128] = e1 * inv;
    p[t + 256] = e2 * inv;
    p[t + 384] = e3 * inv;
}

// ---------------------------------------------------------------------------
// Deterministic 2-stage BatchNorm stats.
// ---------------------------------------------------------------------------
__global__ __launch_bounds__(256)
void bn_stage1(const float* __restrict__ WX, float* __restrict__ psum,
               float* __restrict__ psq)
{
    const int blk = blockIdx.x;
    const int t   = threadIdx.x;
    const float* base = WX + (size_t)blk * 32 * HH;
    float s0 = 0.f, s1 = 0.f, q0 = 0.f, q1 = 0.f;
    for (int r = 0; r < 32; r++) {
        float a0 = base[(size_t)r * HH + t];
        float a1 = base[(size_t)r * HH + t + 256];
        s0 += a0; q0 = fmaf(a0, a0, q0);
        s1 += a1; q1 = fmaf(a1, a1, q1);
    }
    psum[(size_t)blk * HH + t]       = s0;
    psum[(size_t)blk * HH + t + 256] = s1;
    psq [(size_t)blk * HH + t]       = q0;
    psq [(size_t)blk * HH + t + 256] = q1;
}

__global__ __launch_bounds__(512)
void bn_stage2(const float* __restrict__ psum, const float* __restrict__ psq,
               float* __restrict__ sum, float* __restrict__ sq)
{
    const int h = threadIdx.x;
    float s = 0.f, q = 0.f;
    for (int i = 0; i < 256; i++) {
        s += psum[(size_t)i * HH + h];
        q += psq [(size_t)i * HH + h];
    }
    sum[h] = s;
    sq[h]  = q;
}

// ---------------------------------------------------------------------------
// Fused BN + LIF scan.
// ---------------------------------------------------------------------------
__global__ __launch_bounds__(256)
void lif_kernel(const float* __restrict__ WX,
                const float* __restrict__ sum, const float* __restrict__ sq,
                const float* __restrict__ gamma, const float* __restrict__ beta,
                float* __restrict__ out)
{
    const int g = blockIdx.x * blockDim.x + threadIdx.x;
    const int b = g >> 9;
    const int h = g & 511;

    const float inv_n = 1.0f / (float)BT;
    float mu  = sum[h] * inv_n;
    float var = fmaf(-mu, mu, sq[h] * inv_n);
    float scale = gamma[h] * __frsqrt_rn(var + 1e-5f);
    float shift = fmaf(-mu, scale, beta[h]);

    const float* wp = WX  + (size_t)b * TT * HH + h;
    float*       op = out + (size_t)b * TT * HH + h;

    float u = 0.0f;
    for (int t = 0; t < TT; t += 8) {
        float w[8];
        #pragma unroll
        for (int j = 0; j < 8; j++)
            w[j] = wp[(size_t)(t + j) * HH];
        #pragma unroll
        for (int j = 0; j < 8; j++) {
            u = fmaf(0.5f, u, fmaf(w[j], scale, shift));
            float s = (u > 1.0f) ? 1.0f : 0.0f;
            op[(size_t)(t + j) * HH] = s;
            u = (1.0f - s) * u;
        }
    }
}

// ---------------------------------------------------------------------------
// Stream/event context (created once, before graph capture; reused for the
// capture call — the launch DAG is identical on every invocation).
// ---------------------------------------------------------------------------
struct Ctx {
    cudaStream_t s1, s2;
    cudaEvent_t e0, eK, eV;
    Ctx() {
        cudaStreamCreateWithFlags(&s1, cudaStreamNonBlocking);
        cudaStreamCreateWithFlags(&s2, cudaStreamNonBlocking);
        cudaEventCreateWithFlags(&e0, cudaEventDisableTiming);
        cudaEventCreateWithFlags(&eK, cudaEventDisableTiming);
        cudaEventCreateWithFlags(&eV, cudaEventDisableTiming);
    }
};

// ---------------------------------------------------------------------------
// Launch
// ---------------------------------------------------------------------------
extern "C" void kernel_launch(void* const* d_in, const int* in_sizes, int n_in,
                              void* d_out, int out_size)
{
    static Ctx ctx;   // one-time stream/event creation (same work every call)

    const float* v     = (const float*)d_in[0];
    const float* a     = (const float*)d_in[1];
    const float* Wq    = (const float*)d_in[2];
    const float* Wk    = (const float*)d_in[3];
    const float* Wv    = (const float*)d_in[4];
    const float* Wo    = (const float*)d_in[5];
    const float* W     = (const float*)d_in[6];
    const float* gamma = (const float*)d_in[7];
    const float* beta  = (const float*)d_in[8];
    float* out = (float*)d_out;

    float *Q, *K, *V, *O, *X, *WX, *S, *PS, *PQ, *SM, *SQ;
    cudaGetSymbolAddress((void**)&Q,  g_Q);
    cudaGetSymbolAddress((void**)&K,  g_K);
    cudaGetSymbolAddress((void**)&V,  g_V);
    cudaGetSymbolAddress((void**)&O,  g_O);
    cudaGetSymbolAddress((void**)&X,  g_X);
    cudaGetSymbolAddress((void**)&WX, g_WX);
    cudaGetSymbolAddress((void**)&S,  g_S);
    cudaGetSymbolAddress((void**)&PS, g_psum);
    cudaGetSymbolAddress((void**)&PQ, g_psq);
    cudaGetSymbolAddress((void**)&SM, g_sum);
    cudaGetSymbolAddress((void**)&SQ, g_sq);

    const long TH = (long)TT * HH;     // 262144
    const long T2 = (long)TT * TT;     // 262144

    // Dynamic smem: 2 x BK=32 x (132 + (BN+4)) floats
    const int SMEM128 = 2 * 32 * (132 + 132) * 4;   // 67,584 B
    const int SMEM64  = 2 * 32 * (132 + 68)  * 4;   // 51,200 B
    cudaFuncSetAttribute(gemm5<128,8,false,false>,
        cudaFuncAttributeMaxDynamicSharedMemorySize, SMEM128);
    cudaFuncSetAttribute(gemm5<128,8,true,false>,
        cudaFuncAttributeMaxDynamicSharedMemorySize, SMEM128);
    cudaFuncSetAttribute(gemm5<128,8,false,true>,
        cudaFuncAttributeMaxDynamicSharedMemorySize, SMEM128);
    cudaFuncSetAttribute(gemm5<64,4,false,false>,
        cudaFuncAttributeMaxDynamicSharedMemorySize, SMEM64);

    // ---- fork: Q on default stream, K on s1, V on s2
    cudaEventRecord(ctx.e0, 0);
    cudaStreamWaitEvent(ctx.s1, ctx.e0, 0);
    cudaStreamWaitEvent(ctx.s2, ctx.e0, 0);

    gemm5<128,8,false,false><<<dim3(4,64,1), 256, SMEM128, 0>>>(
        v, Wq, Q, nullptr, BT, HH, HH, HH, HH, HH, 1.0f, 1, 0,0,0,0,0,0);
    gemm5<128,8,false,false><<<dim3(4,64,1), 256, SMEM128, ctx.s1>>>(
        a, Wk, K, nullptr, BT, HH, HH, HH, HH, HH, 1.0f, 1, 0,0,0,0,0,0);
    gemm5<128,8,false,false><<<dim3(4,64,1), 256, SMEM128, ctx.s2>>>(
        a, Wv, V, nullptr, BT, HH, HH, HH, HH, HH, 1.0f, 1, 0,0,0,0,0,0);

    cudaEventRecord(ctx.eK, ctx.s1);
    cudaEventRecord(ctx.eV, ctx.s2);

    // scores needs Q (stream 0) + K (eK); V keeps running on s2 underneath
    cudaStreamWaitEvent(0, ctx.eK, 0);
    gemm5<128,8,true,false><<<dim3(4,4,NBH), 256, SMEM128, 0>>>(
        Q, K, S, nullptr, TT, TT, DH, HH, HH, TT, 0.125f,
        NH, TH, DH, TH, DH, (long)NH*T2, T2);

    // softmax (in place) — still overlapping V
    softmax_kernel<<<NBH*TT, 128, 0, 0>>>(S);

    // P@V needs V done
    cudaStreamWaitEvent(0, ctx.eV, 0);
    gemm5<64,4,false,false><<<dim3(1,4,NBH), 256, SMEM64, 0>>>(
        S, V, O, nullptr, TT, DH, TT, TT, HH, HH, 1.0f,
        NH, (long)NH*T2, T2, TH, DH, TH, DH);

    // X = O @ Wo + a
    gemm5<128,8,false,true><<<dim3(4,64,1), 256, SMEM128, 0>>>(
        O, Wo, X, a, BT, HH, HH, HH, HH, HH, 1.0f, 1, 0,0,0,0,0,0);

    // WX = X @ W
    gemm5<128,8,false,false><<<dim3(4,64,1), 256, SMEM128, 0>>>(
        X, W, WX, nullptr, BT, HH, HH, HH, HH, HH, 1.0f, 1, 0,0,0,0,0,0);

    // BN stats (deterministic) + fused BN/LIF
    bn_stage1<<<256, 256, 0, 0>>>(WX, PS, PQ);
    bn_stage2<<<1, 512, 0, 0>>>(PS, PQ, SM, SQ);
    lif_kernel<<<32, 256, 0, 0>>>(WX, SM, SQ, gamma, beta, out);
}

// round 14
// speedup vs baseline: 1.7482x; 1.0315x over previous
#include <cuda_runtime.h>
#include <cstdint>

// Problem dims (fixed by the reference)
#define BB   16
#define TT   512
#define HH   512
#define BT   (BB*TT)        // 8192
#define NH   8
#define DH   64             // head dim
#define NBH  (BB*NH)        // 128 batched attention mats

typedef unsigned long long ull;

// ---------------------------------------------------------------------------
// Scratch (static device globals — no allocation)
// ---------------------------------------------------------------------------
__device__ float g_Q [(size_t)BT*HH];
__device__ float g_K [(size_t)BT*HH];
__device__ float g_V [(size_t)BT*HH];
__device__ float g_O [(size_t)BT*HH];
__device__ float g_X [(size_t)BT*HH];
__device__ float g_WX[(size_t)BT*HH];
__device__ float g_S [(size_t)NBH*TT*TT];     // 134 MB attention scores
__device__ float g_psum[(size_t)256*HH];
__device__ float g_psq [(size_t)256*HH];
__device__ float g_sum [HH];
__device__ float g_sq  [HH];

// ---------------------------------------------------------------------------
// f32x2 packed math (sm_103a FFMA2 — PTX-only)
// ---------------------------------------------------------------------------
__device__ __forceinline__ ull pack2(float x, float y) {
    ull r; asm("mov.b64 %0, {%1, %2};" : "=l"(r) : "f"(x), "f"(y)); return r;
}
__device__ __forceinline__ ull ffma2(ull a, ull b, ull c) {
    ull d; asm("fma.rn.f32x2 %0, %1, %2, %3;" : "=l"(d) : "l"(a), "l"(b), "l"(c));
    return d;
}
__device__ __forceinline__ void unpack2(ull v, float& x, float& y) {
    asm("mov.b64 {%0, %1}, %2;" : "=f"(x), "=f"(y) : "l"(v));
}

// ---------------------------------------------------------------------------
// Accurate expf, immune to --use_fast_math.
// ---------------------------------------------------------------------------
__device__ __forceinline__ float exp_acc(float x) {
    x = fmaxf(x, -87.0f);
    float z = x * 1.44269504088896341f;
    float n = rintf(z);
    float f = fmaf(n, -0.693145751953125f, x);
    f = fmaf(n, -1.428606765330187e-06f, f);
    float p = 1.9841269841e-4f;
    p = fmaf(p, f, 1.3888888889e-3f);
    p = fmaf(p, f, 8.3333333333e-3f);
    p = fmaf(p, f, 4.1666666667e-2f);
    p = fmaf(p, f, 1.6666666667e-1f);
    p = fmaf(p, f, 0.5f);
    p = fmaf(p, f, 1.0f);
    p = fmaf(p, f, 1.0f);
    int ni = (int)n;
    float sc = __int_as_float((ni + 127) << 23);
    return p * sc;
}

// ---------------------------------------------------------------------------
// fp32 GEMM, f32x2 accumulation — ROUND-4 CHAMPION CORE, UNCHANGED.
//   BM=128, BK=16, 256 threads, TM=8, TN(8|4), double-buffered smem,
//   2 CTAs/SM. (Measured: 92 µs / 512-K GEMM, fma=60.6%.)
// ---------------------------------------------------------------------------
template<int BN, int TN, bool TRANSB, bool RESID>
__global__ __launch_bounds__(256, 2)
void gemm4(const float* __restrict__ A, const float* __restrict__ Bm,
           float* __restrict__ C, const float* __restrict__ R,
           int M, int N, int K, int lda, int ldb, int ldc, float alpha,
           int heads, long sAb, long sAh, long sBb, long sBh,
           long sCb, long sCh)
{
    constexpr int BM = 128, BK = 16;
    constexpr int NPAIR = TN / 2;
    constexpr int BQ = BN / 4;
    constexpr int AS_ST = BM + 4;                 // 132
    constexpr int BS_ST = BN + 4;
    constexpr int ASZ = BK * AS_ST;
    constexpr int BSZ = BK * BS_ST;
    constexpr int BIT = (BK * BQ + 255) / 256;

    extern __shared__ __align__(16) float sm[];  // [A0][A1][B0][B1]

    const int z = blockIdx.z;
    const int zb = z / heads, zh = z % heads;
    A  += (size_t)zb * sAb + (size_t)zh * sAh;
    Bm += (size_t)zb * sBb + (size_t)zh * sBh;
    const size_t coff = (size_t)zb * sCb + (size_t)zh * sCh;

    const int tid = threadIdx.x;
    const int tx  = tid & 15;
    const int ty  = tid >> 4;
    const int m0  = blockIdx.y * BM;
    const int n0  = blockIdx.x * BN;

    const int ar = tid >> 2;             // 0..63
    const int aq = tid & 3;              // float4 index along K

    float4 pa[2], pb[2];

    auto loadA = [&](int k0) {
        #pragma unroll
        for (int it = 0; it < 2; it++)
            pa[it] = *reinterpret_cast<const float4*>(
                &A[(size_t)(m0 + ar + it * 64) * lda + k0 + aq * 4]);
    };
    auto loadB = [&](int k0) {
        if (TRANSB) {
            #pragma unroll
            for (int it = 0; it < 2; it++)
                pb[it] = *reinterpret_cast<const float4*>(
                    &Bm[(size_t)(n0 + ar + it * 64) * ldb + k0 + aq * 4]);
        } else {
            #pragma unroll
            for (int it = 0; it < BIT; it++) {
                int idx = tid + it * 256;
                int kk = idx / BQ, nn = idx % BQ;
                pb[it] = *reinterpret_cast<const float4*>(
                    &Bm[(size_t)(k0 + kk) * ldb + n0 + nn * 4]);
            }
        }
    };
    auto storeTiles = [&](int buf) {
        float* As = sm + buf * ASZ;
        float* Bs = sm + 2 * ASZ + buf * BSZ;
        #pragma unroll
        for (int it = 0; it < 2; it++) {
            As[(aq*4 + 0) * AS_ST + ar + it*64] = pa[it].x;
            As[(aq*4 + 1) * AS_ST + ar + it*64] = pa[it].y;
            As[(aq*4 + 2) * AS_ST + ar + it*64] = pa[it].z;
            As[(aq*4 + 3) * AS_ST + ar + it*64] = pa[it].w;
        }
        if (TRANSB) {
            #pragma unroll
            for (int it = 0; it < 2; it++) {
                Bs[(aq*4 + 0) * BS_ST + ar + it*64] = pb[it].x;
                Bs[(aq*4 + 1) * BS_ST + ar + it*64] = pb[it].y;
                Bs[(aq*4 + 2) * BS_ST + ar + it*64] = pb[it].z;
                Bs[(aq*4 + 3) * BS_ST + ar + it*64] = pb[it].w;
            }
        } else {
            #pragma unroll
            for (int it = 0; it < BIT; it++) {
                int idx = tid + it * 256;
                int kk = idx / BQ, nn = idx % BQ;
                *reinterpret_cast<float4*>(&Bs[kk * BS_ST + nn * 4]) = pb[it];
            }
        }
    };

    ull acc[8][NPAIR];
    #pragma unroll
    for (int i = 0; i < 8; i++)
        #pragma unroll
        for (int j = 0; j < NPAIR; j++) acc[i][j] = 0ull;

    loadA(0); loadB(0);
    storeTiles(0);
    __syncthreads();
    int buf = 0;

    for (int k0 = 0; k0 < K; k0 += BK) {
        const int kn = k0 + BK;
        if (kn < K) { loadA(kn); loadB(kn); }

        const float* As = sm + buf * ASZ;
        const float* Bs = sm + 2 * ASZ + buf * BSZ;

        #pragma unroll
        for (int kk = 0; kk < BK; kk++) {
            float4 av0 = *reinterpret_cast<const float4*>(&As[kk * AS_ST + ty * 4]);
            float4 av1 = *reinterpret_cast<const float4*>(&As[kk * AS_ST + ty * 4 + 64]);
            float a8[8] = {av0.x, av0.y, av0.z, av0.w,
                           av1.x, av1.y, av1.z, av1.w};
            ull aa[8];
            #pragma unroll
            for (int i = 0; i < 8; i++) aa[i] = pack2(a8[i], a8[i]);

            ull bp[NPAIR];
            {
                ulonglong2 b0 = *reinterpret_cast<const ulonglong2*>(&Bs[kk * BS_ST + tx * 4]);
                bp[0] = b0.x; bp[1] = b0.y;
                if (TN == 8) {
                    ulonglong2 b1 = *reinterpret_cast<const ulonglong2*>(&Bs[kk * BS_ST + tx * 4 + 64]);
                    bp[2] = b1.x; bp[3] = b1.y;
                }
            }
            #pragma unroll
            for (int i = 0; i < 8; i++)
                #pragma unroll
                for (int j = 0; j < NPAIR; j++)
                    acc[i][j] = ffma2(aa[i], bp[j], acc[i][j]);
        }

        if (kn < K) {
            storeTiles(buf ^ 1);
            __syncthreads();
            buf ^= 1;
        }
    }

    // ---- epilogue
    C += coff;
    if (RESID) R += coff;
    #pragma unroll
    for (int i = 0; i < 8; i++) {
        int row = m0 + ty * 4 + (i & 3) + ((i >> 2) * 64);
        #pragma unroll
        for (int g = 0; g < TN / 4; g++) {
            size_t off = (size_t)row * ldc + n0 + tx * 4 + g * 64;
            float4 o;
            unpack2(acc[i][2*g + 0], o.x, o.y);
            unpack2(acc[i][2*g + 1], o.z, o.w);
            o.x *= alpha; o.y *= alpha; o.z *= alpha; o.w *= alpha;
            if (RESID) {
                float4 rv = *reinterpret_cast<const float4*>(&R[off]);
                o.x += rv.x; o.y += rv.y; o.z += rv.z; o.w += rv.w;
            }
            *reinterpret_cast<float4*>(&C[off]) = o;
        }
    }
}

// ---------------------------------------------------------------------------
// Row softmax over last dim (512). One block (128 thr) per row, in place.
// ---------------------------------------------------------------------------
__global__ __launch_bounds__(128)
void softmax_kernel(float* __restrict__ S)
{
    __shared__ float red[8];
    const int t = threadIdx.x;
    float* p = S + (size_t)blockIdx.x * 512;

    float x0 = p[t], x1 = p[t + 128], x2 = p[t + 256], x3 = p[t + 384];
    float m = fmaxf(fmaxf(x0, x1), fmaxf(x2, x3));
    #pragma unroll
    for (int o = 16; o; o >>= 1)
        m = fmaxf(m, __shfl_xor_sync(0xffffffffu, m, o));
    if ((t & 31) == 0) red[t >> 5] = m;
    __syncthreads();
    m = fmaxf(fmaxf(red[0], red[1]), fmaxf(red[2], red[3]));

    float e0 = exp_acc(x0 - m), e1 = exp_acc(x1 - m);
    float e2 = exp_acc(x2 - m), e3 = exp_acc(x3 - m);
    float s = (e0 + e1) + (e2 + e3);
    #pragma unroll
    for (int o = 16; o; o >>= 1)
        s += __shfl_xor_sync(0xffffffffu, s, o);
    if ((t & 31) == 0) red[4 + (t >> 5)] = s;
    __syncthreads();
    s = (red[4] + red[5]) + (red[6] + red[7]);

    float inv = 1.0f / s;
    p[t]       = e0 * inv;
    p[t + 128] = e1 * inv;
    p[t + 256] = e2 * inv;
    p[t + 384] = e3 * inv;
}

// ---------------------------------------------------------------------------
// Deterministic 2-stage BatchNorm stats.
// ---------------------------------------------------------------------------
__global__ __launch_bounds__(256)
void bn_stage1(const float* __restrict__ WX, float* __restrict__ psum,
               float* __restrict__ psq)
{
    const int blk = blockIdx.x;
    const int t   = threadIdx.x;
    const float* base = WX + (size_t)blk * 32 * HH;
    float s0 = 0.f, s1 = 0.f, q0 = 0.f, q1 = 0.f;
    for (int r = 0; r < 32; r++) {
        float a0 = base[(size_t)r * HH + t];
        float a1 = base[(size_t)r * HH + t + 256];
        s0 += a0; q0 = fmaf(a0, a0, q0);
        s1 += a1; q1 = fmaf(a1, a1, q1);
    }
    psum[(size_t)blk * HH + t]       = s0;
    psum[(size_t)blk * HH + t + 256] = s1;
    psq [(size_t)blk * HH + t]       = q0;
    psq [(size_t)blk * HH + t + 256] = q1;
}

__global__ __launch_bounds__(512)
void bn_stage2(const float* __restrict__ psum, const float* __restrict__ psq,
               float* __restrict__ sum, float* __restrict__ sq)
{
    const int h = threadIdx.x;
    float s = 0.f, q = 0.f;
    for (int i = 0; i < 256; i++) {
        s += psum[(size_t)i * HH + h];
        q += psq [(size_t)i * HH + h];
    }
    sum[h] = s;
    sq[h]  = q;
}

// ---------------------------------------------------------------------------
// Fused BN + LIF scan.
// ---------------------------------------------------------------------------
__global__ __launch_bounds__(256)
void lif_kernel(const float* __restrict__ WX,
                const float* __restrict__ sum, const float* __restrict__ sq,
                const float* __restrict__ gamma, const float* __restrict__ beta,
                float* __restrict__ out)
{
    const int g = blockIdx.x * blockDim.x + threadIdx.x;
    const int b = g >> 9;
    const int h = g & 511;

    const float inv_n = 1.0f / (float)BT;
    float mu  = sum[h] * inv_n;
    float var = fmaf(-mu, mu, sq[h] * inv_n);
    float scale = gamma[h] * __frsqrt_rn(var + 1e-5f);
    float shift = fmaf(-mu, scale, beta[h]);

    const float* wp = WX  + (size_t)b * TT * HH + h;
    float*       op = out + (size_t)b * TT * HH + h;

    float u = 0.0f;
    for (int t = 0; t < TT; t += 8) {
        float w[8];
        #pragma unroll
        for (int j = 0; j < 8; j++)
            w[j] = wp[(size_t)(t + j) * HH];
        #pragma unroll
        for (int j = 0; j < 8; j++) {
            u = fmaf(0.5f, u, fmaf(w[j], scale, shift));
            float s = (u > 1.0f) ? 1.0f : 0.0f;
            op[(size_t)(t + j) * HH] = s;
            u = (1.0f - s) * u;
        }
    }
}

// ---------------------------------------------------------------------------
// Stream/event context (created once; DAG identical on every call).
// ---------------------------------------------------------------------------
struct Ctx {
    cudaStream_t s1, s2;
    cudaEvent_t e0, eK, eV;
    Ctx() {
        cudaStreamCreateWithFlags(&s1, cudaStreamNonBlocking);
        cudaStreamCreateWithFlags(&s2, cudaStreamNonBlocking);
        cudaEventCreateWithFlags(&e0, cudaEventDisableTiming);
        cudaEventCreateWithFlags(&eK, cudaEventDisableTiming);
        cudaEventCreateWithFlags(&eV, cudaEventDisableTiming);
    }
};

// ---------------------------------------------------------------------------
// Launch
// ---------------------------------------------------------------------------
extern "C" void kernel_launch(void* const* d_in, const int* in_sizes, int n_in,
                              void* d_out, int out_size)
{
    static Ctx ctx;   // one-time stream/event creation

    const float* v     = (const float*)d_in[0];
    const float* a     = (const float*)d_in[1];
    const float* Wq    = (const float*)d_in[2];
    const float* Wk    = (const float*)d_in[3];
    const float* Wv    = (const float*)d_in[4];
    const float* Wo    = (const float*)d_in[5];
    const float* W     = (const float*)d_in[6];
    const float* gamma = (const float*)d_in[7];
    const float* beta  = (const float*)d_in[8];
    float* out = (float*)d_out;

    float *Q, *K, *V, *O, *X, *WX, *S, *PS, *PQ, *SM, *SQ;
    cudaGetSymbolAddress((void**)&Q,  g_Q);
    cudaGetSymbolAddress((void**)&K,  g_K);
    cudaGetSymbolAddress((void**)&V,  g_V);
    cudaGetSymbolAddress((void**)&O,  g_O);
    cudaGetSymbolAddress((void**)&X,  g_X);
    cudaGetSymbolAddress((void**)&WX, g_WX);
    cudaGetSymbolAddress((void**)&S,  g_S);
    cudaGetSymbolAddress((void**)&PS, g_psum);
    cudaGetSymbolAddress((void**)&PQ, g_psq);
    cudaGetSymbolAddress((void**)&SM, g_sum);
    cudaGetSymbolAddress((void**)&SQ, g_sq);

    const long TH = (long)TT * HH;     // 262144
    const long T2 = (long)TT * TT;     // 262144

    // Dynamic smem: 2 A-bufs (16x132) + 2 B-bufs (16x(BN+4)) floats
    const int SMEM128 = (2 * 16 * 132 + 2 * 16 * 132) * 4;   // 33,792 B
    const int SMEM64  = (2 * 16 * 132 + 2 * 16 * 68)  * 4;   // 25,600 B

    // ---- fork: Q on default stream, K on s1, V on s2
    cudaEventRecord(ctx.e0, 0);
    cudaStreamWaitEvent(ctx.s1, ctx.e0, 0);
    cudaStreamWaitEvent(ctx.s2, ctx.e0, 0);

    gemm4<128,8,false,false><<<dim3(4,64,1), 256, SMEM128, 0>>>(
        v, Wq, Q, nullptr, BT, HH, HH, HH, HH, HH, 1.0f, 1, 0,0,0,0,0,0);
    gemm4<128,8,false,false><<<dim3(4,64,1), 256, SMEM128, ctx.s1>>>(
        a, Wk, K, nullptr, BT, HH, HH, HH, HH, HH, 1.0f, 1, 0,0,0,0,0,0);
    gemm4<128,8,false,false><<<dim3(4,64,1), 256, SMEM128, ctx.s2>>>(
        a, Wv, V, nullptr, BT, HH, HH, HH, HH, HH, 1.0f, 1, 0,0,0,0,0,0);

    cudaEventRecord(ctx.eK, ctx.s1);
    cudaEventRecord(ctx.eV, ctx.s2);

    // scores needs Q (stream 0) + K (eK); V keeps running on s2 underneath
    cudaStreamWaitEvent(0, ctx.eK, 0);
    gemm4<128,8,true,false><<<dim3(4,4,NBH), 256, SMEM128, 0>>>(
        Q, K, S, nullptr, TT, TT, DH, HH, HH, TT, 0.125f,
        NH, TH, DH, TH, DH, (long)NH*T2, T2);

    // softmax (in place) — still overlapping V
    softmax_kernel<<<NBH*TT, 128, 0, 0>>>(S);

    // P@V needs V done
    cudaStreamWaitEvent(0, ctx.eV, 0);
    gemm4<64,4,false,false><<<dim3(1,4,NBH), 256, SMEM64, 0>>>(
        S, V, O, nullptr, TT, DH, TT, TT, HH, HH, 1.0f,
        NH, (long)NH*T2, T2, TH, DH, TH, DH);

    // X = O @ Wo + a
    gemm4<128,8,false,true><<<dim3(4,64,1), 256, SMEM128, 0>>>(
        O, Wo, X, a, BT, HH, HH, HH, HH, HH, 1.0f, 1, 0,0,0,0,0,0);

    // WX = X @ W
    gemm4<128,8,false,false><<<dim3(4,64,1), 256, SMEM128, 0>>>(
        X, W, WX, nullptr, BT, HH, HH, HH, HH, HH, 1.0f, 1, 0,0,0,0,0,0);

    // BN stats (deterministic) + fused BN/LIF
    bn_stage1<<<256, 256, 0, 0>>>(WX, PS, PQ);
    bn_stage2<<<1, 512, 0, 0>>>(PS, PQ, SM, SQ);
    lif_kernel<<<32, 256, 0, 0>>>(WX, SM, SQ, gamma, beta, out);
}